// round 13
// baseline (speedup 1.0000x reference)
#include <cuda_runtime.h>
#include <cuda_bf16.h>
#include <cstdint>
#include <math.h>

#define N_NODES 50000
#define N_EDGES 800000
#define E2 (N_EDGES + N_NODES)
#define H 128
#define HV (H / 4)          // float4s per row
#define IN_DIM 64
#define KIN (IN_DIM + H)    // 192
#define NEG_SLOPE 0.2f

// ---------------- scratch (device globals) ----------------
// fp32 buffer ids: 0=z, 1=b0, 2=b1, 3=xw, 4=hL
__device__ float4        g_buf[5][(size_t)N_NODES * HV];
// bf16 hi/lo mirrors of activations that feed GEMMs (ids 0,1,2,4 used)
__device__ __nv_bfloat16 g_bh[5][(size_t)N_NODES * H];
__device__ __nv_bfloat16 g_bl[5][(size_t)N_NODES * H];
// pre-split encoder input [x|h] (selector 5)
__device__ __nv_bfloat16 g_inh[(size_t)N_NODES * KIN];
__device__ __nv_bfloat16 g_inl[(size_t)N_NODES * KIN];
// pre-split weights: 0=enc(192) 1..3=Wg(128) 4=Wd(256) 5=Wd1(128)
__device__ __nv_bfloat16 g_wh[6][128 * 256];
__device__ __nv_bfloat16 g_wl[6][128 * 256];

__device__ float  g_asv[N_NODES];
__device__ float  g_adv[N_NODES];
__device__ int    g_off[N_NODES + 1];
__device__ int    g_cur[N_NODES];
__device__ int    g_csrc[E2];
__device__ float  g_hbar[H];

__device__ __forceinline__ const __nv_bfloat16* bufH(int s) { return (s == 5) ? g_inh : g_bh[s]; }
__device__ __forceinline__ const __nv_bfloat16* bufL(int s) { return (s == 5) ? g_inl : g_bl[s]; }

// ---------------- split helpers ----------------
__device__ __forceinline__ void split_pair(float x, float y,
                                           __nv_bfloat162* hi, __nv_bfloat162* lo) {
    __nv_bfloat16 hx = __float2bfloat16(x), hy = __float2bfloat16(y);
    __nv_bfloat16 lx = __float2bfloat16(x - __bfloat162float(hx));
    __nv_bfloat16 ly = __float2bfloat16(y - __bfloat162float(hy));
    *hi = __halves2bfloat162(hx, hy);
    *lo = __halves2bfloat162(ly == ly ? lx : lx, ly);   // (no-op guard elided by compiler)
}

// ---------------- edge_index dtype sniff ----------------
__device__ __forceinline__ bool ei_is64(const int* __restrict__ e32) {
    bool z = true;
    #pragma unroll
    for (int i = 0; i < 8; i++) z = z && (e32[2 * i + 1] == 0);
    return z;
}
__device__ __forceinline__ int ei_at(const int* __restrict__ e32, int elem, bool is64) {
    return is64 ? e32[2 * elem] : e32[elem];
}

// ---------------- small utils ----------------
__global__ void zero_i_kernel(int n) {
    int i = blockIdx.x * blockDim.x + threadIdx.x;
    if (i < n) g_cur[i] = 0;
}
__global__ void zero_hbar_kernel() {
    int i = threadIdx.x;
    if (i < H) g_hbar[i] = 0.f;
}

// ---------------- up-front splits ----------------
// weights: linear copy-split of 'elems' floats into g_wh/g_wl[widx]
__global__ void split_w_kernel(const float* __restrict__ W, int elems, int widx) {
    int id = blockIdx.x * blockDim.x + threadIdx.x;
    int e = id * 4;
    if (e >= elems) return;
    float4 v = *(const float4*)(W + e);
    __nv_bfloat162 h0, l0, h1, l1;
    split_pair(v.x, v.y, &h0, &l0);
    split_pair(v.z, v.w, &h1, &l1);
    *(__nv_bfloat162*)&g_wh[widx][e]     = h0;
    *(__nv_bfloat162*)&g_wh[widx][e + 2] = h1;
    *(__nv_bfloat162*)&g_wl[widx][e]     = l0;
    *(__nv_bfloat162*)&g_wl[widx][e + 2] = l1;
}

// encoder input: concat [x(64) | h(128)] rows -> g_inh/g_inl (stride 192)
__global__ void split_in_kernel(const float* __restrict__ x, const float* __restrict__ h) {
    int id = blockIdx.x * blockDim.x + threadIdx.x;       // one per 4 elems
    int total = N_NODES * (KIN / 4);
    if (id >= total) return;
    int n = id / (KIN / 4);
    int c4 = (id % (KIN / 4)) * 4;
    float4 v;
    if (c4 < IN_DIM) v = *(const float4*)(x + (size_t)n * IN_DIM + c4);
    else             v = *(const float4*)(h + (size_t)n * H + (c4 - IN_DIM));
    __nv_bfloat162 h0, l0, h1, l1;
    split_pair(v.x, v.y, &h0, &l0);
    split_pair(v.z, v.w, &h1, &l1);
    size_t o = (size_t)n * KIN + c4;
    *(__nv_bfloat162*)&g_inh[o]     = h0;
    *(__nv_bfloat162*)&g_inh[o + 2] = h1;
    *(__nv_bfloat162*)&g_inl[o]     = l0;
    *(__nv_bfloat162*)&g_inl[o + 2] = l1;
}

// ---------------- CSR build ----------------
__global__ void hist_kernel(const int* __restrict__ e32) {
    int e = blockIdx.x * blockDim.x + threadIdx.x;
    if (e >= E2) return;
    bool is64 = ei_is64(e32);
    int dst = (e < N_EDGES) ? ei_at(e32, N_EDGES + e, is64) : (e - N_EDGES);
    if ((unsigned)dst < (unsigned)N_NODES) atomicAdd(&g_cur[dst], 1);
}

__global__ void scan_kernel() {
    __shared__ int wsum[32];
    __shared__ int carry_s;
    int t = threadIdx.x, lane = t & 31, w = t >> 5;
    if (t == 0) carry_s = 0;
    __syncthreads();
    for (int base = 0; base < N_NODES; base += 1024) {
        int idx = base + t;
        int v = (idx < N_NODES) ? g_cur[idx] : 0;
        int x = v;
        #pragma unroll
        for (int o = 1; o < 32; o <<= 1) {
            int y = __shfl_up_sync(0xffffffffu, x, o);
            if (lane >= o) x += y;
        }
        if (lane == 31) wsum[w] = x;
        __syncthreads();
        if (w == 0) {
            int y = wsum[lane];
            int z = y;
            #pragma unroll
            for (int o = 1; o < 32; o <<= 1) {
                int q = __shfl_up_sync(0xffffffffu, z, o);
                if (lane >= o) z += q;
            }
            wsum[lane] = z - y;
        }
        __syncthreads();
        int incl = x + wsum[w];
        int excl = incl - v;
        int c = carry_s;
        if (idx < N_NODES) {
            g_off[idx] = c + excl;
            g_cur[idx] = c + excl;
        }
        __syncthreads();
        if (t == 1023) carry_s = c + incl;
        __syncthreads();
    }
    if (t == 0) g_off[N_NODES] = carry_s;
}

__global__ void scatter_kernel(const int* __restrict__ e32) {
    int e = blockIdx.x * blockDim.x + threadIdx.x;
    if (e >= E2) return;
    bool is64 = ei_is64(e32);
    int src, dst;
    if (e < N_EDGES) {
        src = ei_at(e32, e, is64);
        dst = ei_at(e32, N_EDGES + e, is64);
    } else {
        src = e - N_EDGES; dst = src;
    }
    if ((unsigned)dst >= (unsigned)N_NODES) return;
    if ((unsigned)src >= (unsigned)N_NODES) src = 0;
    int pos = atomicAdd(&g_cur[dst], 1);
    g_csrc[pos] = src;
}

// ---------------- tensor-core GEMM (bf16x3 split, pre-split operands) ----------------
// C[n,128] = concat(A0[:,:K0], A1[:,:K-K0]) @ W[128,K]^T (+bias)(+relu)(+bf16-split out)
#define TS 128
#define SKP 40   // bf16 smem row stride

__device__ __forceinline__ void ldsm4(uint32_t* r, uint32_t addr) {
    asm volatile("ldmatrix.sync.aligned.m8n8.x4.shared.b16 {%0,%1,%2,%3}, [%4];"
                 : "=r"(r[0]), "=r"(r[1]), "=r"(r[2]), "=r"(r[3]) : "r"(addr));
}
__device__ __forceinline__ void ldsm2(uint32_t* r, uint32_t addr) {
    asm volatile("ldmatrix.sync.aligned.m8n8.x2.shared.b16 {%0,%1}, [%2];"
                 : "=r"(r[0]), "=r"(r[1]) : "r"(addr));
}
__device__ __forceinline__ void mma16816(float* d, const uint32_t* a, const uint32_t* b) {
    asm volatile("mma.sync.aligned.m16n8k16.row.col.f32.bf16.bf16.f32 "
                 "{%0,%1,%2,%3}, {%4,%5,%6,%7}, {%8,%9}, {%0,%1,%2,%3};"
                 : "+f"(d[0]), "+f"(d[1]), "+f"(d[2]), "+f"(d[3])
                 : "r"(a[0]), "r"(a[1]), "r"(a[2]), "r"(a[3]), "r"(b[0]), "r"(b[1]));
}

__global__ __launch_bounds__(256, 2) void gemm_tc_kernel(
    int a0s, int a1s, int K0, int K, int widx,
    const float* __restrict__ bias, int cs,
    int n, int doRelu, int doSplit)
{
    const __nv_bfloat16* __restrict__ A0h = bufH(a0s);
    const __nv_bfloat16* __restrict__ A0l = bufL(a0s);
    const __nv_bfloat16* __restrict__ A1h = bufH(a1s);
    const __nv_bfloat16* __restrict__ A1l = bufL(a1s);
    const __nv_bfloat16* __restrict__ Wh_ = g_wh[widx];
    const __nv_bfloat16* __restrict__ Wl_ = g_wl[widx];
    float* __restrict__ C = (float*)g_buf[cs];

    __shared__ __align__(16) __nv_bfloat16 sAh[128 * SKP];
    __shared__ __align__(16) __nv_bfloat16 sAl[128 * SKP];
    __shared__ __align__(16) __nv_bfloat16 sBh[128 * SKP];
    __shared__ __align__(16) __nv_bfloat16 sBl[128 * SKP];

    int t = threadIdx.x, lane = t & 31, warp = t >> 5;
    int wm = warp & 3;        // 0..3 -> M
    int wn = warp >> 2;       // 0..1 -> N
    int row0 = blockIdx.x * TS;
    int K1 = K - K0;

    float acc[2][8][4];
    #pragma unroll
    for (int mt = 0; mt < 2; mt++)
        #pragma unroll
        for (int nt = 0; nt < 8; nt++)
            #pragma unroll
            for (int q = 0; q < 4; q++) acc[mt][nt][q] = 0.f;

    uint32_t baseAh = (uint32_t)__cvta_generic_to_shared(sAh);
    uint32_t baseAl = (uint32_t)__cvta_generic_to_shared(sAl);
    uint32_t baseBh = (uint32_t)__cvta_generic_to_shared(sBh);
    uint32_t baseBl = (uint32_t)__cvta_generic_to_shared(sBl);

    int aRow = lane & 15, aK = (lane >> 4) << 3;
    int bN = lane & 7,  bK = lane & 8;

    for (int k0 = 0; k0 < K; k0 += 32) {
        // ---- stage pre-split bf16 tiles: pure copies ----
        #pragma unroll
        for (int i = 0; i < 2; i++) {
            int id = i * 256 + t;          // 0..511
            int r  = id >> 2;              // 0..127
            int c8 = (id & 3) * 8;         // 0,8,16,24
            int k  = k0 + c8;
            uint4 vh = make_uint4(0, 0, 0, 0), vl = make_uint4(0, 0, 0, 0);
            int gr = row0 + r;
            if (gr < n) {
                if (k < K0) {
                    vh = *(const uint4*)(A0h + (size_t)gr * K0 + k);
                    vl = *(const uint4*)(A0l + (size_t)gr * K0 + k);
                } else {
                    vh = *(const uint4*)(A1h + (size_t)gr * K1 + (k - K0));
                    vl = *(const uint4*)(A1l + (size_t)gr * K1 + (k - K0));
                }
            }
            *(uint4*)&sAh[r * SKP + c8] = vh;
            *(uint4*)&sAl[r * SKP + c8] = vl;
            uint4 wh = *(const uint4*)(Wh_ + (size_t)r * K + k);
            uint4 wl = *(const uint4*)(Wl_ + (size_t)r * K + k);
            *(uint4*)&sBh[r * SKP + c8] = wh;
            *(uint4*)&sBl[r * SKP + c8] = wl;
        }
        __syncthreads();

        // ---- compute ----
        #pragma unroll
        for (int ks = 0; ks < 2; ks++) {
            int kk = ks * 16;
            uint32_t ah[2][4], al[2][4];
            #pragma unroll
            for (int mt = 0; mt < 2; mt++) {
                uint32_t off = (uint32_t)((wm * 32 + mt * 16 + aRow) * SKP + kk + aK) * 2u;
                ldsm4(ah[mt], baseAh + off);
                ldsm4(al[mt], baseAl + off);
            }
            #pragma unroll
            for (int nt = 0; nt < 8; nt++) {
                uint32_t boff = (uint32_t)((wn * 64 + nt * 8 + bN) * SKP + kk + bK) * 2u;
                uint32_t bh2[2], bl2[2];
                ldsm2(bh2, baseBh + boff);
                ldsm2(bl2, baseBl + boff);
                #pragma unroll
                for (int mt = 0; mt < 2; mt++) {
                    mma16816(acc[mt][nt], ah[mt], bh2);   // hi*hi
                    mma16816(acc[mt][nt], ah[mt], bl2);   // hi*lo
                    mma16816(acc[mt][nt], al[mt], bh2);   // lo*hi
                }
            }
        }
        __syncthreads();
    }

    // ---- epilogue: fp32 out (+ optional bf16 split out) ----
    #pragma unroll
    for (int mt = 0; mt < 2; mt++) {
        #pragma unroll
        for (int nt = 0; nt < 8; nt++) {
            int r = row0 + wm * 32 + mt * 16 + (lane >> 2);
            int c = wn * 64 + nt * 8 + (lane & 3) * 2;
            float d0 = acc[mt][nt][0], d1 = acc[mt][nt][1];
            float d2 = acc[mt][nt][2], d3 = acc[mt][nt][3];
            if (bias) {
                float b0 = bias[c], b1 = bias[c + 1];
                d0 += b0; d1 += b1; d2 += b0; d3 += b1;
            }
            if (doRelu) {
                d0 = fmaxf(d0, 0.f); d1 = fmaxf(d1, 0.f);
                d2 = fmaxf(d2, 0.f); d3 = fmaxf(d3, 0.f);
            }
            if (r < n) {
                *(float2*)(C + (size_t)r * H + c) = make_float2(d0, d1);
                if (doSplit) {
                    __nv_bfloat162 hh, ll;
                    split_pair(d0, d1, &hh, &ll);
                    *(__nv_bfloat162*)&g_bh[cs][(size_t)r * H + c] = hh;
                    *(__nv_bfloat162*)&g_bl[cs][(size_t)r * H + c] = ll;
                }
            }
            if (r + 8 < n) {
                *(float2*)(C + (size_t)(r + 8) * H + c) = make_float2(d2, d3);
                if (doSplit) {
                    __nv_bfloat162 hh, ll;
                    split_pair(d2, d3, &hh, &ll);
                    *(__nv_bfloat162*)&g_bh[cs][(size_t)(r + 8) * H + c] = hh;
                    *(__nv_bfloat162*)&g_bl[cs][(size_t)(r + 8) * H + c] = ll;
                }
            }
        }
    }
}

// ---------------- per-node attention scalars ----------------
__global__ void attvec_kernel(const float* __restrict__ a_s,
                              const float* __restrict__ a_d)
{
    int wid = (blockIdx.x * blockDim.x + threadIdx.x) >> 5;
    int lane = threadIdx.x & 31;
    if (wid >= N_NODES) return;
    float4 x = g_buf[3][(size_t)wid * HV + lane];
    float4 a = *(const float4*)(a_s + lane * 4);
    float4 b = *(const float4*)(a_d + lane * 4);
    float s = x.x * a.x + x.y * a.y + x.z * a.z + x.w * a.w;
    float d = x.x * b.x + x.y * b.y + x.z * b.z + x.w * b.w;
    #pragma unroll
    for (int o = 16; o; o >>= 1) {
        s += __shfl_xor_sync(0xffffffffu, s, o);
        d += __shfl_xor_sync(0xffffffffu, d, o);
    }
    if (lane == 0) { g_asv[wid] = s; g_adv[wid] = d; }
}

// ---------------- GAT aggregation (softmax over incoming edges, warp per node) ----------------
__global__ void gat_aggr_kernel(const float* __restrict__ bias, int outSel, int doRelu)
{
    float4* __restrict__ outp = g_buf[outSel];
    const float4* __restrict__ xw = g_buf[3];
    int wid = (blockIdx.x * blockDim.x + threadIdx.x) >> 5;
    int lane = threadIdx.x & 31;
    if (wid >= N_NODES) return;
    int s = g_off[wid], e_end = g_off[wid + 1];
    float advv = g_adv[wid];

    float m = -3.4e38f;
    for (int e = s + lane; e < e_end; e += 32) {
        float v = g_asv[g_csrc[e]] + advv;
        v = (v > 0.f) ? v : NEG_SLOPE * v;
        m = fmaxf(m, v);
    }
    #pragma unroll
    for (int o = 16; o; o >>= 1) m = fmaxf(m, __shfl_xor_sync(0xffffffffu, m, o));

    float den = 0.f;
    for (int e = s + lane; e < e_end; e += 32) {
        float v = g_asv[g_csrc[e]] + advv;
        v = (v > 0.f) ? v : NEG_SLOPE * v;
        den += __expf(v - m);
    }
    #pragma unroll
    for (int o = 16; o; o >>= 1) den += __shfl_xor_sync(0xffffffffu, den, o);
    float inv = 1.f / den;

    float4 acc = make_float4(0.f, 0.f, 0.f, 0.f);
    for (int e = s; e < e_end; e++) {
        int src = g_csrc[e];
        float v = g_asv[src] + advv;
        v = (v > 0.f) ? v : NEG_SLOPE * v;
        float w = __expf(v - m) * inv;
        float4 xv = xw[(size_t)src * HV + lane];
        acc.x += w * xv.x; acc.y += w * xv.y; acc.z += w * xv.z; acc.w += w * xv.w;
    }
    float4 b = *(const float4*)(bias + lane * 4);
    acc.x += b.x; acc.y += b.y; acc.z += b.z; acc.w += b.w;
    if (doRelu) {
        acc.x = fmaxf(acc.x, 0.f); acc.y = fmaxf(acc.y, 0.f);
        acc.z = fmaxf(acc.z, 0.f); acc.w = fmaxf(acc.w, 0.f);
    }
    outp[(size_t)wid * HV + lane] = acc;

    // split for downstream GEMM consumption
    __nv_bfloat162 h0, l0, h1, l1;
    split_pair(acc.x, acc.y, &h0, &l0);
    split_pair(acc.z, acc.w, &h1, &l1);
    size_t o = (size_t)wid * H + lane * 4;
    *(__nv_bfloat162*)&g_bh[outSel][o]     = h0;
    *(__nv_bfloat162*)&g_bh[outSel][o + 2] = h1;
    *(__nv_bfloat162*)&g_bl[outSel][o]     = l0;
    *(__nv_bfloat162*)&g_bl[outSel][o + 2] = l1;
}

// ---------------- decoder head ----------------
__global__ void head_y_kernel(const float* __restrict__ Wh,
                              const float* __restrict__ bh,
                              float* __restrict__ y)
{
    int wid = (blockIdx.x * blockDim.x + threadIdx.x) >> 5;
    int lane = threadIdx.x & 31;
    if (wid >= N_NODES) return;
    float4 x = g_buf[3][(size_t)wid * HV + lane];
    float4 w = *(const float4*)(Wh + lane * 4);
    float s = x.x * w.x + x.y * w.y + x.z * w.z + x.w * w.w;
    #pragma unroll
    for (int o = 16; o; o >>= 1) s += __shfl_xor_sync(0xffffffffu, s, o);
    if (lane == 0) y[wid] = 1.f / (1.f + __expf(-(s + bh[0])));
}

// ---------------- mean over nodes of hL -> g_hbar ----------------
__global__ void hbar_acc_kernel() {
    const float* hL = (const float*)g_buf[4];
    int c = threadIdx.x;
    int start = blockIdx.x * 256;
    float s = 0.f;
    for (int i = 0; i < 256; i++) {
        int node = start + i;
        if (node < N_NODES) s += hL[(size_t)node * H + c];
    }
    atomicAdd(&g_hbar[c], s);
}

__global__ void term_kernel(const float* __restrict__ Wt,
                            const float* __restrict__ bt,
                            float* __restrict__ tout)
{
    __shared__ float sm[H];
    int c = threadIdx.x;
    sm[c] = g_hbar[c] * (1.f / (float)N_NODES) * Wt[c];
    __syncthreads();
    for (int o = 64; o; o >>= 1) {
        if (c < o) sm[c] += sm[c + o];
        __syncthreads();
    }
    if (c == 0) tout[0] = 1.f / (1.f + __expf(-(sm[0] + bt[0])));
}

// ---------------- copy hL into output slot ----------------
__global__ void copy_hl_kernel(float* __restrict__ dst) {
    const float* hL = (const float*)g_buf[4];
    size_t i = (size_t)blockIdx.x * blockDim.x + threadIdx.x;
    size_t total = (size_t)N_NODES * H;
    for (; i < total; i += (size_t)gridDim.x * blockDim.x) dst[i] = hL[i];
}

// ---------------- launch ----------------
extern "C" void kernel_launch(void* const* d_in, const int* in_sizes, int n_in,
                              void* d_out, int out_size)
{
    const float* x       = (const float*)d_in[0];
    const float* h       = (const float*)d_in[1];
    const int*   ei32    = (const int*)d_in[2];
    const float* W_enc   = (const float*)d_in[3];
    const float* b_enc   = (const float*)d_in[4];
    const float* Wg      = (const float*)d_in[5];
    const float* att_src = (const float*)d_in[6];
    const float* att_dst = (const float*)d_in[7];
    const float* bg      = (const float*)d_in[8];
    const float* Wd      = (const float*)d_in[9];
    const float* bd      = (const float*)d_in[10];
    const float* Wd1     = (const float*)d_in[11];
    const float* bd1     = (const float*)d_in[12];
    const float* Wh      = (const float*)d_in[13];
    const float* bh      = (const float*)d_in[14];
    const float* Wt      = (const float*)d_in[15];
    const float* bt      = (const float*)d_in[16];
    float*       out     = (float*)d_out;

    const int TPB = 256;
    int grid_nodes_w = (N_NODES * 32 + TPB - 1) / TPB;
    int grid_edges   = (E2 + TPB - 1) / TPB;
    int grid_gemm    = (N_NODES + TS - 1) / TS;

    // ---- up-front operand splits ----
    split_in_kernel<<<(N_NODES * (KIN / 4) + TPB - 1) / TPB, TPB>>>(x, h);
    split_w_kernel<<<(128 * KIN / 4 + TPB - 1) / TPB, TPB>>>(W_enc, 128 * KIN, 0);
    for (int i = 0; i < 3; i++)
        split_w_kernel<<<(128 * H / 4 + TPB - 1) / TPB, TPB>>>(Wg + (size_t)i * H * H, 128 * H, 1 + i);
    split_w_kernel<<<(128 * 2 * H / 4 + TPB - 1) / TPB, TPB>>>(Wd, 128 * 2 * H, 4);
    split_w_kernel<<<(128 * H / 4 + TPB - 1) / TPB, TPB>>>(Wd1, 128 * H, 5);

    // ---- CSR build ----
    zero_i_kernel<<<(N_NODES + TPB - 1) / TPB, TPB>>>(N_NODES);
    hist_kernel<<<grid_edges, TPB>>>(ei32);
    scan_kernel<<<1, 1024>>>();
    scatter_kernel<<<grid_edges, TPB>>>(ei32);

    // ---- encoder: z(=buf0) = [x|h] @ W_enc^T + b_enc  (split out: feeds GEMMs) ----
    gemm_tc_kernel<<<grid_gemm, 256>>>(5, 5, KIN, KIN, 0, b_enc, 0, N_NODES, 0, 1);

    // ---- GAT processor: xw(=buf3) = cur @ Wg_i^T ; aggr -> next ----
    int inSel[4]  = { 0, 1, 2, 1 };
    int outSel[4] = { 1, 2, 1, 4 };
    int layer_idx[4] = { 0, 1, 2, 2 };
    for (int li = 0; li < 4; li++) {
        int i = layer_idx[li];
        gemm_tc_kernel<<<grid_gemm, 256>>>(inSel[li], inSel[li], H, H, 1 + i,
                                           (const float*)0, 3, N_NODES, 0, 0);
        attvec_kernel<<<grid_nodes_w, TPB>>>(att_src + (size_t)i * H, att_dst + (size_t)i * H);
        gat_aggr_kernel<<<grid_nodes_w, TPB>>>(bg + (size_t)i * H, outSel[li], (li < 3) ? 1 : 0);
    }

    // ---- decoder: d1(=buf2) = relu([hL|z] @ Wd^T + bd) (split, feeds d2) ----
    gemm_tc_kernel<<<grid_gemm, 256>>>(4, 0, H, 2 * H, 4, bd, 2, N_NODES, 1, 1);
    //      d2(=buf3) = relu(d1 @ Wd1^T + bd1)
    gemm_tc_kernel<<<grid_gemm, 256>>>(2, 2, H, H, 5, bd1, 3, N_NODES, 1, 0);
    head_y_kernel<<<grid_nodes_w, TPB>>>(Wh, bh, out);

    // ---- termination scalar ----
    zero_hbar_kernel<<<1, 128>>>();
    hbar_acc_kernel<<<(N_NODES + 255) / 256, 128>>>();
    term_kernel<<<1, 128>>>(Wt, bt, out + N_NODES);

    // ---- hL -> out[N+1 ...] ----
    copy_hl_kernel<<<1024, 256>>>(out + N_NODES + 1);
}

// round 15
// speedup vs baseline: 1.2063x; 1.2063x over previous
#include <cuda_runtime.h>
#include <cuda_bf16.h>
#include <cstdint>
#include <math.h>

#define N_NODES 50000
#define N_EDGES 800000
#define E2 (N_EDGES + N_NODES)
#define H 128
#define HV (H / 4)          // float4s per row
#define IN_DIM 64
#define NEG_SLOPE 0.2f

// ---------------- scratch (device globals; 16B-aligned via float4) ----------------
// buffer ids: 0=z, 1=b0, 2=b1, 3=xw, 4=hL
__device__ float4 g_buf[5][(size_t)N_NODES * HV];
__device__ float  g_asv[N_NODES];
__device__ float  g_adv[N_NODES];
__device__ int    g_off[N_NODES + 1];
__device__ int    g_cur[N_NODES];
__device__ int    g_csrc[E2];
__device__ float  g_hbar[H];

__device__ __forceinline__ float* bufF(int s) { return (float*)g_buf[s]; }

// ---------------- edge_index dtype sniff ----------------
__device__ __forceinline__ bool ei_is64(const int* __restrict__ e32) {
    bool z = true;
    #pragma unroll
    for (int i = 0; i < 8; i++) z = z && (e32[2 * i + 1] == 0);
    return z;
}
__device__ __forceinline__ int ei_at(const int* __restrict__ e32, int elem, bool is64) {
    return is64 ? e32[2 * elem] : e32[elem];
}

// ---------------- small utils ----------------
__global__ void zero_i_kernel(int n) {
    int i = blockIdx.x * blockDim.x + threadIdx.x;
    if (i < n) g_cur[i] = 0;
}
__global__ void zero_att_kernel() {
    int i = blockIdx.x * blockDim.x + threadIdx.x;
    if (i < N_NODES) { g_asv[i] = 0.f; g_adv[i] = 0.f; }
}
__global__ void zero_hbar_kernel() {
    int i = threadIdx.x;
    if (i < H) g_hbar[i] = 0.f;
}

// ---------------- CSR build ----------------
__global__ void hist_kernel(const int* __restrict__ e32) {
    int e = blockIdx.x * blockDim.x + threadIdx.x;
    if (e >= E2) return;
    bool is64 = ei_is64(e32);
    int dst = (e < N_EDGES) ? ei_at(e32, N_EDGES + e, is64) : (e - N_EDGES);
    if ((unsigned)dst < (unsigned)N_NODES) atomicAdd(&g_cur[dst], 1);
}

__global__ void scan_kernel() {
    __shared__ int wsum[32];
    __shared__ int carry_s;
    int t = threadIdx.x, lane = t & 31, w = t >> 5;
    if (t == 0) carry_s = 0;
    __syncthreads();
    for (int base = 0; base < N_NODES; base += 1024) {
        int idx = base + t;
        int v = (idx < N_NODES) ? g_cur[idx] : 0;
        int x = v;
        #pragma unroll
        for (int o = 1; o < 32; o <<= 1) {
            int y = __shfl_up_sync(0xffffffffu, x, o);
            if (lane >= o) x += y;
        }
        if (lane == 31) wsum[w] = x;
        __syncthreads();
        if (w == 0) {
            int y = wsum[lane];
            int z = y;
            #pragma unroll
            for (int o = 1; o < 32; o <<= 1) {
                int q = __shfl_up_sync(0xffffffffu, z, o);
                if (lane >= o) z += q;
            }
            wsum[lane] = z - y;
        }
        __syncthreads();
        int incl = x + wsum[w];
        int excl = incl - v;
        int c = carry_s;
        if (idx < N_NODES) {
            g_off[idx] = c + excl;
            g_cur[idx] = c + excl;
        }
        __syncthreads();
        if (t == 1023) carry_s = c + incl;
        __syncthreads();
    }
    if (t == 0) g_off[N_NODES] = carry_s;
}

__global__ void scatter_kernel(const int* __restrict__ e32) {
    int e = blockIdx.x * blockDim.x + threadIdx.x;
    if (e >= E2) return;
    bool is64 = ei_is64(e32);
    int src, dst;
    if (e < N_EDGES) {
        src = ei_at(e32, e, is64);
        dst = ei_at(e32, N_EDGES + e, is64);
    } else {
        src = e - N_EDGES; dst = src;
    }
    if ((unsigned)dst >= (unsigned)N_NODES) return;
    if ((unsigned)src >= (unsigned)N_NODES) src = 0;
    int pos = atomicAdd(&g_cur[dst], 1);
    g_csrc[pos] = src;
}

// ---------------- tensor-core GEMM (bf16x3 split, mma.sync m16n8k16) ----------------
// C[n,128] = concat(A0[:,:K0], A1[:,:K-K0]) @ W[128,K]^T (+bias)(+relu)(+fused att dots)
#define TS 128
#define SKP 40   // bf16 smem row stride (80B: conflict-free ldmatrix phases)

__device__ __forceinline__ void ldsm4(uint32_t* r, uint32_t addr) {
    asm volatile("ldmatrix.sync.aligned.m8n8.x4.shared.b16 {%0,%1,%2,%3}, [%4];"
                 : "=r"(r[0]), "=r"(r[1]), "=r"(r[2]), "=r"(r[3]) : "r"(addr));
}
__device__ __forceinline__ void ldsm2(uint32_t* r, uint32_t addr) {
    asm volatile("ldmatrix.sync.aligned.m8n8.x2.shared.b16 {%0,%1}, [%2];"
                 : "=r"(r[0]), "=r"(r[1]) : "r"(addr));
}
__device__ __forceinline__ void mma16816(float* d, const uint32_t* a, const uint32_t* b) {
    asm volatile("mma.sync.aligned.m16n8k16.row.col.f32.bf16.bf16.f32 "
                 "{%0,%1,%2,%3}, {%4,%5,%6,%7}, {%8,%9}, {%0,%1,%2,%3};"
                 : "+f"(d[0]), "+f"(d[1]), "+f"(d[2]), "+f"(d[3])
                 : "r"(a[0]), "r"(a[1]), "r"(a[2]), "r"(a[3]), "r"(b[0]), "r"(b[1]));
}
__device__ __forceinline__ void split_pair(float x, float y,
                                           __nv_bfloat162* hi, __nv_bfloat162* lo) {
    __nv_bfloat16 hx = __float2bfloat16(x), hy = __float2bfloat16(y);
    __nv_bfloat16 lx = __float2bfloat16(x - __bfloat162float(hx));
    __nv_bfloat16 ly = __float2bfloat16(y - __bfloat162float(hy));
    *hi = __halves2bfloat162(hx, hy);
    *lo = __halves2bfloat162(lx, ly);
}

__global__ __launch_bounds__(256, 2) void gemm_tc_kernel(
    const float* A0e, const float* A1e, int a0s, int a1s,
    int K0, int K, const float* __restrict__ W,
    const float* __restrict__ bias, int cs,
    int n, int doRelu,
    const float* __restrict__ a_s, const float* __restrict__ a_d, int doAtt)
{
    const float* __restrict__ A0 = A0e ? A0e : bufF(a0s);
    const float* __restrict__ A1 = A1e ? A1e : bufF(a1s);
    float* __restrict__ C = bufF(cs);

    __shared__ __align__(16) __nv_bfloat16 sAh[128 * SKP];
    __shared__ __align__(16) __nv_bfloat16 sAl[128 * SKP];
    __shared__ __align__(16) __nv_bfloat16 sBh[128 * SKP];
    __shared__ __align__(16) __nv_bfloat16 sBl[128 * SKP];

    int t = threadIdx.x, lane = t & 31, warp = t >> 5;
    int wm = warp & 3;        // 0..3 -> M
    int wn = warp >> 2;       // 0..1 -> N
    int row0 = blockIdx.x * TS;
    int K1 = K - K0;

    float acc[2][8][4];
    #pragma unroll
    for (int mt = 0; mt < 2; mt++)
        #pragma unroll
        for (int nt = 0; nt < 8; nt++)
            #pragma unroll
            for (int q = 0; q < 4; q++) acc[mt][nt][q] = 0.f;

    uint32_t baseAh = (uint32_t)__cvta_generic_to_shared(sAh);
    uint32_t baseAl = (uint32_t)__cvta_generic_to_shared(sAl);
    uint32_t baseBh = (uint32_t)__cvta_generic_to_shared(sBh);
    uint32_t baseBl = (uint32_t)__cvta_generic_to_shared(sBl);

    int aRow = lane & 15, aK = (lane >> 4) << 3;   // ldmatrix x4 lane mapping
    int bN = lane & 7,  bK = lane & 8;             // ldmatrix x2: lanes 0-7 -> k+0, 8-15 -> k+8

    for (int k0 = 0; k0 < K; k0 += 32) {
        // ---- stage + split tiles: A[128 x 32], W[128 x 32] ----
        #pragma unroll
        for (int i = 0; i < 4; i++) {
            int id = i * 256 + t;          // 0..1023
            int r  = id >> 3;              // 0..127
            int c4 = (id & 7) * 4;         // 0..28
            int k  = k0 + c4;
            float4 v = make_float4(0.f, 0.f, 0.f, 0.f);
            int gr = row0 + r;
            if (gr < n) {
                if (k < K0) v = *(const float4*)(A0 + (size_t)gr * K0 + k);
                else        v = *(const float4*)(A1 + (size_t)gr * K1 + (k - K0));
            }
            __nv_bfloat162 h0, l0, h1, l1;
            split_pair(v.x, v.y, &h0, &l0);
            split_pair(v.z, v.w, &h1, &l1);
            *(__nv_bfloat162*)&sAh[r * SKP + c4]     = h0;
            *(__nv_bfloat162*)&sAh[r * SKP + c4 + 2] = h1;
            *(__nv_bfloat162*)&sAl[r * SKP + c4]     = l0;
            *(__nv_bfloat162*)&sAl[r * SKP + c4 + 2] = l1;
            float4 wv = *(const float4*)(W + (size_t)r * K + k);
            split_pair(wv.x, wv.y, &h0, &l0);
            split_pair(wv.z, wv.w, &h1, &l1);
            *(__nv_bfloat162*)&sBh[r * SKP + c4]     = h0;
            *(__nv_bfloat162*)&sBh[r * SKP + c4 + 2] = h1;
            *(__nv_bfloat162*)&sBl[r * SKP + c4]     = l0;
            *(__nv_bfloat162*)&sBl[r * SKP + c4 + 2] = l1;
        }
        __syncthreads();

        // ---- compute: 2 k-sub x 8 n-tiles x 2 m-tiles x 3 split-mmas ----
        #pragma unroll
        for (int ks = 0; ks < 2; ks++) {
            int kk = ks * 16;
            uint32_t ah[2][4], al[2][4];
            #pragma unroll
            for (int mt = 0; mt < 2; mt++) {
                uint32_t off = (uint32_t)((wm * 32 + mt * 16 + aRow) * SKP + kk + aK) * 2u;
                ldsm4(ah[mt], baseAh + off);
                ldsm4(al[mt], baseAl + off);
            }
            #pragma unroll
            for (int nt = 0; nt < 8; nt++) {
                uint32_t boff = (uint32_t)((wn * 64 + nt * 8 + bN) * SKP + kk + bK) * 2u;
                uint32_t bh2[2], bl2[2];
                ldsm2(bh2, baseBh + boff);
                ldsm2(bl2, baseBl + boff);
                #pragma unroll
                for (int mt = 0; mt < 2; mt++) {
                    mma16816(acc[mt][nt], ah[mt], bh2);   // hi*hi
                    mma16816(acc[mt][nt], ah[mt], bl2);   // hi*lo
                    mma16816(acc[mt][nt], al[mt], bh2);   // lo*hi
                }
            }
        }
        __syncthreads();
    }

    // ---- fused attention dots: asv/adv += row . a_s/a_d (pre-bias, pre-relu; GAT GEMMs have neither) ----
    if (doAtt) {
        #pragma unroll
        for (int mt = 0; mt < 2; mt++) {
            float ps0 = 0.f, pd0 = 0.f, ps1 = 0.f, pd1 = 0.f;
            #pragma unroll
            for (int nt = 0; nt < 8; nt++) {
                int c = wn * 64 + nt * 8 + (lane & 3) * 2;
                float as0 = a_s[c], as1 = a_s[c + 1];
                float ad0 = a_d[c], ad1 = a_d[c + 1];
                ps0 += acc[mt][nt][0] * as0 + acc[mt][nt][1] * as1;
                pd0 += acc[mt][nt][0] * ad0 + acc[mt][nt][1] * ad1;
                ps1 += acc[mt][nt][2] * as0 + acc[mt][nt][3] * as1;
                pd1 += acc[mt][nt][2] * ad0 + acc[mt][nt][3] * ad1;
            }
            #pragma unroll
            for (int o = 1; o < 4; o <<= 1) {
                ps0 += __shfl_xor_sync(0xffffffffu, ps0, o);
                pd0 += __shfl_xor_sync(0xffffffffu, pd0, o);
                ps1 += __shfl_xor_sync(0xffffffffu, ps1, o);
                pd1 += __shfl_xor_sync(0xffffffffu, pd1, o);
            }
            if ((lane & 3) == 0) {
                int r = row0 + wm * 32 + mt * 16 + (lane >> 2);
                if (r < n)     { atomicAdd(&g_asv[r], ps0);     atomicAdd(&g_adv[r], pd0); }
                if (r + 8 < n) { atomicAdd(&g_asv[r + 8], ps1); atomicAdd(&g_adv[r + 8], pd1); }
            }
        }
    }

    // ---- epilogue stores ----
    #pragma unroll
    for (int mt = 0; mt < 2; mt++) {
        #pragma unroll
        for (int nt = 0; nt < 8; nt++) {
            int r = row0 + wm * 32 + mt * 16 + (lane >> 2);
            int c = wn * 64 + nt * 8 + (lane & 3) * 2;
            float d0 = acc[mt][nt][0], d1 = acc[mt][nt][1];
            float d2 = acc[mt][nt][2], d3 = acc[mt][nt][3];
            if (bias) {
                float b0 = bias[c], b1 = bias[c + 1];
                d0 += b0; d1 += b1; d2 += b0; d3 += b1;
            }
            if (doRelu) {
                d0 = fmaxf(d0, 0.f); d1 = fmaxf(d1, 0.f);
                d2 = fmaxf(d2, 0.f); d3 = fmaxf(d3, 0.f);
            }
            if (r < n)     { *(float2*)(C + (size_t)r * H + c) = make_float2(d0, d1); }
            if (r + 8 < n) { *(float2*)(C + (size_t)(r + 8) * H + c) = make_float2(d2, d3); }
        }
    }
}

// ---------------- GAT aggregation: online softmax + gather (warp per node) ----------------
__global__ void gat_aggr_kernel(const float* __restrict__ bias, int outSel, int doRelu,
                                float* __restrict__ outExt)
{
    float4* __restrict__ outp = g_buf[outSel];
    const float4* __restrict__ xw = g_buf[3];
    int wid = (blockIdx.x * blockDim.x + threadIdx.x) >> 5;
    int lane = threadIdx.x & 31;
    if (wid >= N_NODES) return;
    int s = g_off[wid], e_end = g_off[wid + 1];
    float advv = g_adv[wid];

    // online (max, denom) in one pass; finite sentinel keeps all arithmetic NaN-free
    float m = -3.4e38f, den = 0.f;
    for (int e = s + lane; e < e_end; e += 32) {
        float v = g_asv[g_csrc[e]] + advv;
        v = (v > 0.f) ? v : NEG_SLOPE * v;
        float nm = fmaxf(m, v);
        den = den * __expf(m - nm) + __expf(v - nm);
        m = nm;
    }
    #pragma unroll
    for (int o = 16; o; o >>= 1) {
        float om = __shfl_xor_sync(0xffffffffu, m, o);
        float od = __shfl_xor_sync(0xffffffffu, den, o);
        float nm = fmaxf(m, om);
        den = den * __expf(m - nm) + od * __expf(om - nm);
        m = nm;
    }
    float inv = 1.f / den;

    float4 acc = make_float4(0.f, 0.f, 0.f, 0.f);
    for (int e = s; e < e_end; e++) {
        int src = g_csrc[e];
        float v = g_asv[src] + advv;
        v = (v > 0.f) ? v : NEG_SLOPE * v;
        float w = __expf(v - m) * inv;
        float4 xv = xw[(size_t)src * HV + lane];
        acc.x += w * xv.x; acc.y += w * xv.y; acc.z += w * xv.z; acc.w += w * xv.w;
    }
    float4 b = *(const float4*)(bias + lane * 4);
    acc.x += b.x; acc.y += b.y; acc.z += b.z; acc.w += b.w;
    if (doRelu) {
        acc.x = fmaxf(acc.x, 0.f); acc.y = fmaxf(acc.y, 0.f);
        acc.z = fmaxf(acc.z, 0.f); acc.w = fmaxf(acc.w, 0.f);
    }
    outp[(size_t)wid * HV + lane] = acc;

    if (outExt) {   // final layer: also write hL into the (unaligned) output slot
        float* o = outExt + (size_t)wid * H + lane * 4;
        o[0] = acc.x; o[1] = acc.y; o[2] = acc.z; o[3] = acc.w;
    }
}

// ---------------- decoder head ----------------
__global__ void head_y_kernel(const float* __restrict__ Wh,
                              const float* __restrict__ bh,
                              float* __restrict__ y)
{
    int wid = (blockIdx.x * blockDim.x + threadIdx.x) >> 5;
    int lane = threadIdx.x & 31;
    if (wid >= N_NODES) return;
    float4 x = g_buf[3][(size_t)wid * HV + lane];
    float4 w = *(const float4*)(Wh + lane * 4);
    float s = x.x * w.x + x.y * w.y + x.z * w.z + x.w * w.w;
    #pragma unroll
    for (int o = 16; o; o >>= 1) s += __shfl_xor_sync(0xffffffffu, s, o);
    if (lane == 0) y[wid] = 1.f / (1.f + __expf(-(s + bh[0])));
}

// ---------------- mean over nodes of hL -> g_hbar ----------------
__global__ void hbar_acc_kernel() {
    const float* hL = (const float*)g_buf[4];
    int c = threadIdx.x;
    int start = blockIdx.x * 256;
    float s = 0.f;
    for (int i = 0; i < 256; i++) {
        int node = start + i;
        if (node < N_NODES) s += hL[(size_t)node * H + c];
    }
    atomicAdd(&g_hbar[c], s);
}

__global__ void term_kernel(const float* __restrict__ Wt,
                            const float* __restrict__ bt,
                            float* __restrict__ tout)
{
    __shared__ float sm[H];
    int c = threadIdx.x;
    sm[c] = g_hbar[c] * (1.f / (float)N_NODES) * Wt[c];
    __syncthreads();
    for (int o = 64; o; o >>= 1) {
        if (c < o) sm[c] += sm[c + o];
        __syncthreads();
    }
    if (c == 0) tout[0] = 1.f / (1.f + __expf(-(sm[0] + bt[0])));
}

// ---------------- launch ----------------
extern "C" void kernel_launch(void* const* d_in, const int* in_sizes, int n_in,
                              void* d_out, int out_size)
{
    const float* x       = (const float*)d_in[0];
    const float* h       = (const float*)d_in[1];
    const int*   ei32    = (const int*)d_in[2];
    const float* W_enc   = (const float*)d_in[3];
    const float* b_enc   = (const float*)d_in[4];
    const float* Wg      = (const float*)d_in[5];
    const float* att_src = (const float*)d_in[6];
    const float* att_dst = (const float*)d_in[7];
    const float* bg      = (const float*)d_in[8];
    const float* Wd      = (const float*)d_in[9];
    const float* bd      = (const float*)d_in[10];
    const float* Wd1     = (const float*)d_in[11];
    const float* bd1     = (const float*)d_in[12];
    const float* Wh      = (const float*)d_in[13];
    const float* bh      = (const float*)d_in[14];
    const float* Wt      = (const float*)d_in[15];
    const float* bt      = (const float*)d_in[16];
    float*       out     = (float*)d_out;

    const int TPB = 256;
    int grid_nodes_w = (N_NODES * 32 + TPB - 1) / TPB;
    int grid_nodes   = (N_NODES + TPB - 1) / TPB;
    int grid_edges   = (E2 + TPB - 1) / TPB;
    int grid_gemm    = (N_NODES + TS - 1) / TS;
    const float* NUL = (const float*)0;
    float* NULM = (float*)0;

    // ---- CSR build ----
    zero_i_kernel<<<grid_nodes, TPB>>>(N_NODES);
    hist_kernel<<<grid_edges, TPB>>>(ei32);
    scan_kernel<<<1, 1024>>>();
    scatter_kernel<<<grid_edges, TPB>>>(ei32);

    // ---- encoder: z(=buf0) = [x|h] @ W_enc^T + b_enc ----
    gemm_tc_kernel<<<grid_gemm, 256>>>(x, h, 0, 0, IN_DIM, IN_DIM + H, W_enc, b_enc, 0,
                                       N_NODES, 0, NUL, NUL, 0);

    // ---- GAT processor ----
    int inSel[4]  = { 0, 1, 2, 1 };
    int outSel[4] = { 1, 2, 1, 4 };
    int layer_idx[4] = { 0, 1, 2, 2 };
    for (int li = 0; li < 4; li++) {
        int i = layer_idx[li];
        const float* Wi = Wg + (size_t)i * H * H;
        zero_att_kernel<<<grid_nodes, TPB>>>();
        gemm_tc_kernel<<<grid_gemm, 256>>>(NUL, NUL, inSel[li], inSel[li], H, H, Wi, NUL, 3,
                                           N_NODES, 0,
                                           att_src + (size_t)i * H, att_dst + (size_t)i * H, 1);
        gat_aggr_kernel<<<grid_nodes_w, TPB>>>(bg + (size_t)i * H, outSel[li], (li < 3) ? 1 : 0,
                                               (li == 3) ? (out + N_NODES + 1) : NULM);
    }

    // ---- decoder ----
    gemm_tc_kernel<<<grid_gemm, 256>>>(NUL, NUL, 4, 0, H, 2 * H, Wd, bd, 2,
                                       N_NODES, 1, NUL, NUL, 0);
    gemm_tc_kernel<<<grid_gemm, 256>>>(NUL, NUL, 2, 2, H, H, Wd1, bd1, 3,
                                       N_NODES, 1, NUL, NUL, 0);
    head_y_kernel<<<grid_nodes_w, TPB>>>(Wh, bh, out);

    // ---- termination scalar ----
    zero_hbar_kernel<<<1, 128>>>();
    hbar_acc_kernel<<<(N_NODES + 255) / 256, 128>>>();
    term_kernel<<<1, 128>>>(Wt, bt, out + N_NODES);
}